// round 4
// baseline (speedup 1.0000x reference)
#include <cuda_runtime.h>

#define NN 50000
#define NE 800000
#define DD 128

// ---------------- scratch (static device globals; no allocation) ----------------
__device__ int   g_is64;             // 1 if edge_index is int64, 0 if int32
__device__ int   g_total;            // CSR allocation cursor
__device__ int   g_deg[NN];
__device__ int   g_off[NN];          // start of each node's region (order-free)
__device__ int   g_cur[NN];
__device__ float g_invdeg[NN];
__device__ int   g_col[NE];
__device__ float g_agg[(size_t)NN * DD];
__device__ float g_h1 [(size_t)NN * DD];
__device__ float g_h2 [(size_t)NN * DD];

// Buffer selector: 0 -> external x, 1 -> g_h1, 2 -> g_h2 (resolved on device)
__device__ __forceinline__ const float* sel_in(int sel, const float* x) {
    return sel == 0 ? x : (sel == 1 ? (const float*)g_h1 : (const float*)g_h2);
}

// Edge accessors valid for either dtype layout (ei viewed as int32 words).
__device__ __forceinline__ int get_src(const int* __restrict__ ei, int e) {
    return g_is64 ? ei[2 * e] : ei[e];
}
__device__ __forceinline__ int get_dst(const int* __restrict__ ei, int e) {
    return g_is64 ? ei[2 * NE + 2 * e] : ei[NE + e];
}

// ---------------- dtype detection ----------------
__global__ void k_detect(const int* __restrict__ ei) {
    if (threadIdx.x == 0 && blockIdx.x == 0) {
        int acc = 0;
        for (int i = 1; i < 512; i += 2) acc |= ei[i];
        g_is64 = (acc == 0) ? 1 : 0;
    }
}

// ---------------- CSR build ----------------
__global__ void k_zero_deg() {
    int i = blockIdx.x * blockDim.x + threadIdx.x;
    if (i < NN) g_deg[i] = 0;
    if (i == 0) g_total = 0;
}

__global__ void k_hist(const int* __restrict__ ei) {
    int e = blockIdx.x * blockDim.x + threadIdx.x;
    if (e < NE) {
        int d = get_dst(ei, e);
        if ((unsigned)d < NN) atomicAdd(&g_deg[d], 1);
    }
}

// Order-free CSR region allocation: block scan + one atomicAdd per block.
// Offsets are NOT globally sorted — irrelevant, regions are disjoint.
__global__ __launch_bounds__(256) void k_alloc() {
    __shared__ int warp_sums[8];
    __shared__ int block_base;

    int i    = blockIdx.x * 256 + threadIdx.x;
    int lane = threadIdx.x & 31;
    int wid  = threadIdx.x >> 5;

    int d = (i < NN) ? g_deg[i] : 0;

    // warp-inclusive scan
    int sc = d;
#pragma unroll
    for (int o = 1; o < 32; o <<= 1) {
        int v = __shfl_up_sync(0xffffffffu, sc, o);
        if (lane >= o) sc += v;
    }
    if (lane == 31) warp_sums[wid] = sc;
    __syncthreads();

    if (wid == 0) {
        int ws = (lane < 8) ? warp_sums[lane] : 0;
#pragma unroll
        for (int o = 1; o < 8; o <<= 1) {
            int v = __shfl_up_sync(0xffffffffu, ws, o);
            if (lane >= o) ws += v;
        }
        if (lane < 8) warp_sums[lane] = ws;
        if (lane == 7) block_base = atomicAdd(&g_total, ws);
    }
    __syncthreads();

    if (i < NN) {
        int excl = sc - d + (wid > 0 ? warp_sums[wid - 1] : 0) + block_base;
        g_off[i] = excl;
        g_cur[i] = excl;
        g_invdeg[i] = 1.0f / (float)(d > 0 ? d : 1);
    }
}

__global__ void k_fill(const int* __restrict__ ei) {
    int e = blockIdx.x * blockDim.x + threadIdx.x;
    if (e < NE) {
        int d = get_dst(ei, e);
        int s = get_src(ei, e);
        if ((unsigned)d < NN && (unsigned)s < NN) {
            int p = atomicAdd(&g_cur[d], 1);
            g_col[p] = s;
        }
    }
}

// ---------------- mean aggregation: one warp per node ----------------
__global__ __launch_bounds__(256) void k_agg(int sel, const float* __restrict__ x) {
    int node = (blockIdx.x * blockDim.x + threadIdx.x) >> 5;
    int lane = threadIdx.x & 31;
    if (node >= NN) return;

    const float* h = sel_in(sel, x);

    int beg = g_off[node];
    int cnt = g_deg[node];
    int end = beg + cnt;

    // Two independent accumulator sets -> 2 L2 loads in flight per thread.
    float ax0 = 0.f, ay0 = 0.f, az0 = 0.f, aw0 = 0.f;
    float ax1 = 0.f, ay1 = 0.f, az1 = 0.f, aw1 = 0.f;
    int e = beg;
    for (; e + 1 < end; e += 2) {
        int s0 = __ldg(&g_col[e]);
        int s1 = __ldg(&g_col[e + 1]);
        float4 v0 = __ldg(((const float4*)(h + (size_t)s0 * DD)) + lane);
        float4 v1 = __ldg(((const float4*)(h + (size_t)s1 * DD)) + lane);
        ax0 += v0.x; ay0 += v0.y; az0 += v0.z; aw0 += v0.w;
        ax1 += v1.x; ay1 += v1.y; az1 += v1.z; aw1 += v1.w;
    }
    if (e < end) {
        int s0 = __ldg(&g_col[e]);
        float4 v0 = __ldg(((const float4*)(h + (size_t)s0 * DD)) + lane);
        ax0 += v0.x; ay0 += v0.y; az0 += v0.z; aw0 += v0.w;
    }
    float inv = g_invdeg[node];
    float4 o = make_float4((ax0 + ax1) * inv, (ay0 + ay1) * inv,
                           (az0 + az1) * inv, (aw0 + aw1) * inv);
    ((float4*)(g_agg + (size_t)node * DD))[lane] = o;
}

// ---------------- fused GEMM: out = agg @ Wl^T + h @ Wr^T + b (+relu) ----------
// Logical A = [agg | h]  (M x 256),  B[k][o] = Wl[o][k] (k<128) else Wr[o][k-128]
// BM=64, BN=128, BK=32, 256 threads, 8x4 register tile per thread.
__global__ __launch_bounds__(256) void k_gemm(int in_sel, const float* __restrict__ x,
                                              const float* __restrict__ Wl,
                                              const float* __restrict__ bl,
                                              const float* __restrict__ Wr,
                                              int out_sel, float* __restrict__ ext_out,
                                              int relu) {
    __shared__ float As[32][64];
    __shared__ float Bs[32][128];

    const float* A0 = (const float*)g_agg;      // aggregated features
    const float* A1 = sel_in(in_sel, x);        // node's own features
    float* out = out_sel == 0 ? ext_out : (out_sel == 1 ? (float*)g_h1 : (float*)g_h2);

    const int tid = threadIdx.x;
    const int tx  = tid & 31;   // output-dim group (o = tx*4 .. tx*4+3)
    const int ty  = tid >> 5;   // row group (rows ty*8 .. ty*8+7)
    const int blockM = blockIdx.x * 64;

    float acc[8][4];
#pragma unroll
    for (int i = 0; i < 8; ++i)
#pragma unroll
        for (int j = 0; j < 4; ++j) acc[i][j] = 0.f;

    const int lr = tid >> 3;         // 0..31, A-tile row within half
    const int lk = (tid & 7) << 2;   // 0,4,...,28

    for (int kc = 0; kc < 256; kc += 32) {
        const float* A = (kc < 128) ? A0 : A1;
        const float* W = (kc < 128) ? Wl : Wr;
        const int kb = kc & 127;

        // A tile: 64 rows x 32 k, stored transposed As[k][m]
#pragma unroll
        for (int rr = 0; rr < 64; rr += 32) {
            int row = blockM + lr + rr;
            float4 v = make_float4(0.f, 0.f, 0.f, 0.f);
            if (row < NN)
                v = *(const float4*)(A + (size_t)row * DD + kb + lk);
            As[lk + 0][lr + rr] = v.x;
            As[lk + 1][lr + rr] = v.y;
            As[lk + 2][lr + rr] = v.z;
            As[lk + 3][lr + rr] = v.w;
        }
        // B tile: Bs[k][o] = W[o][kb+k]; 128 o x 32 k
#pragma unroll
        for (int it = 0; it < 4; ++it) {
            int idx = tid + it * 256;       // 0..1023
            int o   = idx >> 3;             // 0..127
            int k4  = (idx & 7) << 2;       // 0..28
            float4 v = *(const float4*)(W + o * DD + kb + k4);
            Bs[k4 + 0][o] = v.x;
            Bs[k4 + 1][o] = v.y;
            Bs[k4 + 2][o] = v.z;
            Bs[k4 + 3][o] = v.w;
        }
        __syncthreads();

#pragma unroll
        for (int k = 0; k < 32; ++k) {
            float4 a0 = *(const float4*)&As[k][ty * 8];
            float4 a1 = *(const float4*)&As[k][ty * 8 + 4];
            float4 b  = *(const float4*)&Bs[k][tx * 4];
            float a[8] = {a0.x, a0.y, a0.z, a0.w, a1.x, a1.y, a1.z, a1.w};
#pragma unroll
            for (int i = 0; i < 8; ++i) {
                acc[i][0] += a[i] * b.x;
                acc[i][1] += a[i] * b.y;
                acc[i][2] += a[i] * b.z;
                acc[i][3] += a[i] * b.w;
            }
        }
        __syncthreads();
    }

    float4 bb = *(const float4*)(bl + tx * 4);
#pragma unroll
    for (int i = 0; i < 8; ++i) {
        int row = blockM + ty * 8 + i;
        if (row < NN) {
            float4 o;
            o.x = acc[i][0] + bb.x;
            o.y = acc[i][1] + bb.y;
            o.z = acc[i][2] + bb.z;
            o.w = acc[i][3] + bb.w;
            if (relu) {
                o.x = fmaxf(o.x, 0.f); o.y = fmaxf(o.y, 0.f);
                o.z = fmaxf(o.z, 0.f); o.w = fmaxf(o.w, 0.f);
            }
            *(float4*)(out + (size_t)row * DD + tx * 4) = o;
        }
    }
}

// ---------------- launch (kernel launches ONLY; graph-capture safe) ----------
extern "C" void kernel_launch(void* const* d_in, const int* in_sizes, int n_in,
                              void* d_out, int out_size) {
    const float* x  = (const float*)d_in[0];
    const int*   ei = (const int*)d_in[1];   // int32 words (handles int64 too via g_is64)
    const float* Wl1 = (const float*)d_in[2];
    const float* bl1 = (const float*)d_in[3];
    const float* Wr1 = (const float*)d_in[4];
    const float* Wl2 = (const float*)d_in[5];
    const float* bl2 = (const float*)d_in[6];
    const float* Wr2 = (const float*)d_in[7];
    const float* Wl3 = (const float*)d_in[8];
    const float* bl3 = (const float*)d_in[9];
    const float* Wr3 = (const float*)d_in[10];
    float* out = (float*)d_out;

    // CSR build (reused across all 3 layers)
    k_detect<<<1, 32>>>(ei);
    k_zero_deg<<<(NN + 255) / 256, 256>>>();
    k_hist<<<(NE + 255) / 256, 256>>>(ei);
    k_alloc<<<(NN + 255) / 256, 256>>>();
    k_fill<<<(NE + 255) / 256, 256>>>(ei);

    const int aggGrid  = (NN + 7) / 8;     // 8 warps (nodes) per 256-thread block
    const int gemmGrid = (NN + 63) / 64;

    // Layer 1 (+ReLU): agg(x) -> g_agg; gemm -> g_h1
    k_agg<<<aggGrid, 256>>>(0, x);
    k_gemm<<<gemmGrid, 256>>>(0, x, Wl1, bl1, Wr1, 1, out, 1);
    // Layer 2: agg(g_h1) -> g_agg; gemm -> g_h2
    k_agg<<<aggGrid, 256>>>(1, x);
    k_gemm<<<gemmGrid, 256>>>(1, x, Wl2, bl2, Wr2, 2, out, 0);
    // Layer 3: agg(g_h2) -> g_agg; gemm -> d_out
    k_agg<<<aggGrid, 256>>>(2, x);
    k_gemm<<<gemmGrid, 256>>>(2, x, Wl3, bl3, Wr3, 0, out, 0);
}

// round 6
// speedup vs baseline: 2.1455x; 2.1455x over previous
#include <cuda_runtime.h>
#include <cuda_bf16.h>
#include <cstdint>

#define NN 50000
#define NE 800000
#define DD 128

// ---------------- scratch (static device globals; no allocation) ----------------
__device__ int   g_is64;
__device__ int   g_total;
__device__ int   g_deg[NN];
__device__ int   g_off[NN];
__device__ int   g_cur[NN];
__device__ float g_invdeg[NN];
__device__ int   g_col[NE];
__device__ float g_agg[(size_t)NN * DD];
__device__ float g_h1 [(size_t)NN * DD];
__device__ float g_h2 [(size_t)NN * DD];

__device__ __forceinline__ const float* sel_in(int sel, const float* x) {
    return sel == 0 ? x : (sel == 1 ? (const float*)g_h1 : (const float*)g_h2);
}
__device__ __forceinline__ int get_src(const int* __restrict__ ei, int e) {
    return g_is64 ? ei[2 * e] : ei[e];
}
__device__ __forceinline__ int get_dst(const int* __restrict__ ei, int e) {
    return g_is64 ? ei[2 * NE + 2 * e] : ei[NE + e];
}

// Split a float pair into bf16-hi pair (packed b32) and bf16-lo residual pair.
__device__ __forceinline__ uint32_t pack_hi_lo(float a, float b, uint32_t* lo) {
    __nv_bfloat16 ha = __float2bfloat16_rn(a);
    __nv_bfloat16 hb = __float2bfloat16_rn(b);
    __nv_bfloat16 la = __float2bfloat16_rn(a - __bfloat162float(ha));
    __nv_bfloat16 lb = __float2bfloat16_rn(b - __bfloat162float(hb));
    *lo = ((uint32_t)__bfloat16_as_ushort(lb) << 16) | __bfloat16_as_ushort(la);
    return ((uint32_t)__bfloat16_as_ushort(hb) << 16) | __bfloat16_as_ushort(ha);
}

__device__ __forceinline__ void mma16816(float* d, const uint32_t* a, uint32_t b0, uint32_t b1) {
    asm volatile(
        "mma.sync.aligned.m16n8k16.row.col.f32.bf16.bf16.f32 "
        "{%0,%1,%2,%3}, {%4,%5,%6,%7}, {%8,%9}, {%0,%1,%2,%3};"
        : "+f"(d[0]), "+f"(d[1]), "+f"(d[2]), "+f"(d[3])
        : "r"(a[0]), "r"(a[1]), "r"(a[2]), "r"(a[3]), "r"(b0), "r"(b1));
}

// ---------------- dtype detection ----------------
__global__ void k_detect(const int* __restrict__ ei) {
    if (threadIdx.x == 0 && blockIdx.x == 0) {
        int acc = 0;
        for (int i = 1; i < 512; i += 2) acc |= ei[i];
        g_is64 = (acc == 0) ? 1 : 0;
    }
}

// ---------------- CSR build ----------------
__global__ void k_zero_deg() {
    int i = blockIdx.x * blockDim.x + threadIdx.x;
    if (i < NN) g_deg[i] = 0;
    if (i == 0) g_total = 0;
}
__global__ void k_hist(const int* __restrict__ ei) {
    int e = blockIdx.x * blockDim.x + threadIdx.x;
    if (e < NE) {
        int d = get_dst(ei, e);
        if ((unsigned)d < NN) atomicAdd(&g_deg[d], 1);
    }
}
__global__ __launch_bounds__(256) void k_alloc() {
    __shared__ int warp_sums[8];
    __shared__ int block_base;
    int i = blockIdx.x * 256 + threadIdx.x;
    int lane = threadIdx.x & 31;
    int wid  = threadIdx.x >> 5;
    int d = (i < NN) ? g_deg[i] : 0;
    int sc = d;
#pragma unroll
    for (int o = 1; o < 32; o <<= 1) {
        int v = __shfl_up_sync(0xffffffffu, sc, o);
        if (lane >= o) sc += v;
    }
    if (lane == 31) warp_sums[wid] = sc;
    __syncthreads();
    if (wid == 0) {
        int ws = (lane < 8) ? warp_sums[lane] : 0;
#pragma unroll
        for (int o = 1; o < 8; o <<= 1) {
            int v = __shfl_up_sync(0xffffffffu, ws, o);
            if (lane >= o) ws += v;
        }
        if (lane < 8) warp_sums[lane] = ws;
        if (lane == 7) block_base = atomicAdd(&g_total, ws);
    }
    __syncthreads();
    if (i < NN) {
        int excl = sc - d + (wid > 0 ? warp_sums[wid - 1] : 0) + block_base;
        g_off[i] = excl;
        g_cur[i] = excl;
        g_invdeg[i] = 1.0f / (float)(d > 0 ? d : 1);
    }
}
__global__ void k_fill(const int* __restrict__ ei) {
    int e = blockIdx.x * blockDim.x + threadIdx.x;
    if (e < NE) {
        int d = get_dst(ei, e);
        int s = get_src(ei, e);
        if ((unsigned)d < NN && (unsigned)s < NN) {
            int p = atomicAdd(&g_cur[d], 1);
            g_col[p] = s;
        }
    }
}

// ---------------- mean aggregation: one warp per node (round-3 body) ----------
__global__ __launch_bounds__(256) void k_agg(int sel, const float* __restrict__ x) {
    int node = (blockIdx.x * blockDim.x + threadIdx.x) >> 5;
    int lane = threadIdx.x & 31;
    if (node >= NN) return;
    const float* h = sel_in(sel, x);
    int beg = g_off[node];
    int end = beg + g_deg[node];
    float ax = 0.f, ay = 0.f, az = 0.f, aw = 0.f;
    for (int e = beg; e < end; ++e) {
        int s = g_col[e];
        float4 v = *(((const float4*)(h + (size_t)s * DD)) + lane);
        ax += v.x; ay += v.y; az += v.z; aw += v.w;
    }
    float inv = g_invdeg[node];
    float4 o = make_float4(ax * inv, ay * inv, az * inv, aw * inv);
    ((float4*)(g_agg + (size_t)node * DD))[lane] = o;
}

// ---------------- HMMA bf16-split GEMM ----------------------------------------
// out = agg @ Wl^T + h @ Wr^T + b (+relu), split precision via 3 bf16 products.
// Block: 256 thr, BM=128, BN=128, K chunks of 32 (4 from agg*Wl, 4 from h*Wr).
// Warp tile 32x64: warpM = wid>>1 (4), warpN = wid&1 (2).
// SMEM rows padded to 40 bf16 (20 b32) -> conflict-free fragment loads.
#define KPAD 20   // b32 per SMEM row (32 bf16 data + 8 pad)

__global__ __launch_bounds__(256) void k_gemm_mma(int in_sel, const float* __restrict__ x,
                                                  const float* __restrict__ Wl,
                                                  const float* __restrict__ bl,
                                                  const float* __restrict__ Wr,
                                                  int out_sel, float* __restrict__ ext_out,
                                                  int relu) {
    __shared__ uint32_t AsH[128 * KPAD];
    __shared__ uint32_t AsL[128 * KPAD];
    __shared__ uint32_t BsH[128 * KPAD];
    __shared__ uint32_t BsL[128 * KPAD];

    const int tid  = threadIdx.x;
    const int wid  = tid >> 5;
    const int lane = tid & 31;
    const int warpM = wid >> 1;       // 0..3
    const int warpN = wid & 1;        // 0..1
    const int blockM = blockIdx.x * 128;

    const float* A1 = sel_in(in_sel, x);
    float* outp = out_sel == 0 ? ext_out : (out_sel == 1 ? (float*)g_h1 : (float*)g_h2);

    float acc[2][8][4];
#pragma unroll
    for (int mt = 0; mt < 2; ++mt)
#pragma unroll
        for (int nt = 0; nt < 8; ++nt)
#pragma unroll
            for (int c = 0; c < 4; ++c) acc[mt][nt][c] = 0.f;

    // loader mapping: row/n = tid>>1 (0..127), k-half = (tid&1)*16
    const int ldRow = tid >> 1;
    const int ldK   = (tid & 1) << 4;   // 0 or 16

    for (int kc = 0; kc < 8; ++kc) {
        const float* A = (kc < 4) ? (const float*)g_agg : A1;
        const float* W = (kc < 4) ? Wl : Wr;
        const int kb = (kc & 3) * 32;

        // ---- fill A tile (128 rows x 32 k) ----
        {
            int rg = blockM + ldRow;
            const float* src = A + (size_t)((rg < NN) ? rg : 0) * DD + kb + ldK;
            uint32_t* dh = &AsH[ldRow * KPAD + (ldK >> 1)];
            uint32_t* dl = &AsL[ldRow * KPAD + (ldK >> 1)];
#pragma unroll
            for (int i = 0; i < 8; ++i) {
                float2 f = ((const float2*)src)[i];
                uint32_t lo;
                uint32_t hi = pack_hi_lo(f.x, f.y, &lo);
                dh[i] = hi;
                dl[i] = lo;
            }
        }
        // ---- fill B tile (128 n x 32 k) ----
        {
            const float* src = W + (size_t)ldRow * DD + kb + ldK;
            uint32_t* dh = &BsH[ldRow * KPAD + (ldK >> 1)];
            uint32_t* dl = &BsL[ldRow * KPAD + (ldK >> 1)];
#pragma unroll
            for (int i = 0; i < 8; ++i) {
                float2 f = ((const float2*)src)[i];
                uint32_t lo;
                uint32_t hi = pack_hi_lo(f.x, f.y, &lo);
                dh[i] = hi;
                dl[i] = lo;
            }
        }
        __syncthreads();

        // ---- compute: two k16 steps ----
#pragma unroll
        for (int ks = 0; ks < 2; ++ks) {
            const int kw = ks * 8;   // b32 offset within row
            uint32_t ah[2][4], al[2][4];
#pragma unroll
            for (int mt = 0; mt < 2; ++mt) {
                int row = warpM * 32 + mt * 16 + (lane >> 2);
                int base = row * KPAD + kw + (lane & 3);
                ah[mt][0] = AsH[base];
                ah[mt][1] = AsH[base + 8 * KPAD];
                ah[mt][2] = AsH[base + 4];
                ah[mt][3] = AsH[base + 8 * KPAD + 4];
                al[mt][0] = AsL[base];
                al[mt][1] = AsL[base + 8 * KPAD];
                al[mt][2] = AsL[base + 4];
                al[mt][3] = AsL[base + 8 * KPAD + 4];
            }
#pragma unroll
            for (int nt = 0; nt < 8; ++nt) {
                int n = warpN * 64 + nt * 8 + (lane >> 2);
                int bbase = n * KPAD + kw + (lane & 3);
                uint32_t bh0 = BsH[bbase], bh1 = BsH[bbase + 4];
                uint32_t bl0 = BsL[bbase], bl1 = BsL[bbase + 4];
#pragma unroll
                for (int mt = 0; mt < 2; ++mt) {
                    mma16816(acc[mt][nt], ah[mt], bh0, bh1);   // Ah*Bh
                    mma16816(acc[mt][nt], ah[mt], bl0, bl1);   // Ah*Bl
                    mma16816(acc[mt][nt], al[mt], bh0, bh1);   // Al*Bh
                }
            }
        }
        __syncthreads();
    }

    // ---- epilogue: bias (+relu), direct float2 stores ----
#pragma unroll
    for (int nt = 0; nt < 8; ++nt) {
        int col = warpN * 64 + nt * 8 + (lane & 3) * 2;
        float2 bb = *(const float2*)(bl + col);
#pragma unroll
        for (int mt = 0; mt < 2; ++mt) {
            int row = blockM + warpM * 32 + mt * 16 + (lane >> 2);
            float* d = acc[mt][nt];
            float2 o0 = make_float2(d[0] + bb.x, d[1] + bb.y);
            float2 o1 = make_float2(d[2] + bb.x, d[3] + bb.y);
            if (relu) {
                o0.x = fmaxf(o0.x, 0.f); o0.y = fmaxf(o0.y, 0.f);
                o1.x = fmaxf(o1.x, 0.f); o1.y = fmaxf(o1.y, 0.f);
            }
            if (row < NN)     *(float2*)(outp + (size_t)row * DD + col) = o0;
            if (row + 8 < NN) *(float2*)(outp + (size_t)(row + 8) * DD + col) = o1;
        }
    }
}

// ---------------- launch (kernel launches ONLY; graph-capture safe) ----------
extern "C" void kernel_launch(void* const* d_in, const int* in_sizes, int n_in,
                              void* d_out, int out_size) {
    const float* x  = (const float*)d_in[0];
    const int*   ei = (const int*)d_in[1];
    const float* Wl1 = (const float*)d_in[2];
    const float* bl1 = (const float*)d_in[3];
    const float* Wr1 = (const float*)d_in[4];
    const float* Wl2 = (const float*)d_in[5];
    const float* bl2 = (const float*)d_in[6];
    const float* Wr2 = (const float*)d_in[7];
    const float* Wl3 = (const float*)d_in[8];
    const float* bl3 = (const float*)d_in[9];
    const float* Wr3 = (const float*)d_in[10];
    float* out = (float*)d_out;

    k_detect<<<1, 32>>>(ei);
    k_zero_deg<<<(NN + 255) / 256, 256>>>();
    k_hist<<<(NE + 255) / 256, 256>>>(ei);
    k_alloc<<<(NN + 255) / 256, 256>>>();
    k_fill<<<(NE + 255) / 256, 256>>>(ei);

    const int aggGrid  = (NN + 7) / 8;
    const int gemmGrid = (NN + 127) / 128;   // 391

    k_agg<<<aggGrid, 256>>>(0, x);
    k_gemm_mma<<<gemmGrid, 256>>>(0, x, Wl1, bl1, Wr1, 1, out, 1);
    k_agg<<<aggGrid, 256>>>(1, x);
    k_gemm_mma<<<gemmGrid, 256>>>(1, x, Wl2, bl2, Wr2, 2, out, 0);
    k_agg<<<aggGrid, 256>>>(2, x);
    k_gemm_mma<<<gemmGrid, 256>>>(2, x, Wl3, bl3, Wr3, 0, out, 0);
}